// round 1
// baseline (speedup 1.0000x reference)
#include <cuda_runtime.h>
#include <cstdint>

// Shapes (fixed by the problem):
//   trans_b: [32, 64, 256, 256] fp32 -> 2048 planes of 65536 elements
//   w_down:  [4, 64], b_down: [4], w_up: [64, 4], b_up: [64]
#define NPLANES   2048        // 32 * 64
#define PLANE_F4  16384       // 65536 / 4
#define TOTAL_F4  33554432    // 2048 * 16384

__device__ float g_pooled[NPLANES];
__device__ float g_scale[NPLANES];

// ---------------------------------------------------------------------------
// Kernel 1: per-plane global average pool. One block per (b,c) plane.
// ---------------------------------------------------------------------------
__global__ void __launch_bounds__(256) se_pool_kernel(const float* __restrict__ x)
{
    const int plane = blockIdx.x;
    const float4* __restrict__ p =
        reinterpret_cast<const float4*>(x) + (size_t)plane * PLANE_F4;

    float sum = 0.0f;
    for (int i = threadIdx.x; i < PLANE_F4; i += 256) {
        float4 v = p[i];
        sum += (v.x + v.y) + (v.z + v.w);
    }

    // warp tree
    #pragma unroll
    for (int o = 16; o > 0; o >>= 1)
        sum += __shfl_xor_sync(0xFFFFFFFFu, sum, o);

    __shared__ float s[8];
    const int lane = threadIdx.x & 31;
    const int w    = threadIdx.x >> 5;
    if (lane == 0) s[w] = sum;
    __syncthreads();
    if (w == 0) {
        sum = (lane < 8) ? s[lane] : 0.0f;
        #pragma unroll
        for (int o = 4; o > 0; o >>= 1)
            sum += __shfl_xor_sync(0xFFFFFFFFu, sum, o);
        if (lane == 0)
            g_pooled[plane] = sum * (1.0f / 65536.0f);
    }
}

// ---------------------------------------------------------------------------
// Kernel 2: SE MLP 64 -> 4 (relu) -> 64 (sigmoid). One block per batch.
// ---------------------------------------------------------------------------
__global__ void __launch_bounds__(64) se_mlp_kernel(
    const float* __restrict__ w_down,  // [4, 64]
    const float* __restrict__ b_down,  // [4]
    const float* __restrict__ w_up,    // [64, 4]
    const float* __restrict__ b_up)    // [64]
{
    const int b = blockIdx.x;   // 0..31
    const int c = threadIdx.x;  // 0..63

    __shared__ float pooled[64];
    __shared__ float hidden[4];

    pooled[c] = g_pooled[b * 64 + c];
    __syncthreads();

    if (c < 4) {
        float h = b_down[c];
        #pragma unroll 8
        for (int k = 0; k < 64; k++)
            h = fmaf(pooled[k], w_down[c * 64 + k], h);
        hidden[c] = fmaxf(h, 0.0f);
    }
    __syncthreads();

    float s = b_up[c];
    #pragma unroll
    for (int m = 0; m < 4; m++)
        s = fmaf(hidden[m], w_up[c * 4 + m], s);

    g_scale[b * 64 + c] = 1.0f / (1.0f + expf(-s));
}

// ---------------------------------------------------------------------------
// Kernel 3: elementwise channel rescale. One float4 per thread.
// ---------------------------------------------------------------------------
__global__ void __launch_bounds__(256) se_scale_kernel(
    const float* __restrict__ x, float* __restrict__ y)
{
    const size_t i = (size_t)blockIdx.x * 256 + threadIdx.x;   // float4 index
    const float s = g_scale[i >> 14];                          // 16384 f4/plane
    float4 v = reinterpret_cast<const float4*>(x)[i];
    v.x *= s; v.y *= s; v.z *= s; v.w *= s;
    reinterpret_cast<float4*>(y)[i] = v;
}

// ---------------------------------------------------------------------------
extern "C" void kernel_launch(void* const* d_in, const int* in_sizes, int n_in,
                              void* d_out, int out_size)
{
    const float* trans_b = (const float*)d_in[0];
    const float* w_down  = (const float*)d_in[1];
    const float* b_down  = (const float*)d_in[2];
    const float* w_up    = (const float*)d_in[3];
    const float* b_up    = (const float*)d_in[4];
    float* out = (float*)d_out;

    se_pool_kernel<<<NPLANES, 256>>>(trans_b);
    se_mlp_kernel<<<32, 64>>>(w_down, b_down, w_up, b_up);
    se_scale_kernel<<<TOTAL_F4 / 256, 256>>>(trans_b, out);
}

// round 2
// speedup vs baseline: 1.0112x; 1.0112x over previous
#include <cuda_runtime.h>
#include <cstdint>

// Shapes (fixed by the problem):
//   trans_b: [32, 64, 256, 256] fp32 -> 2048 planes of 65536 elements
//   w_down:  [4, 64], b_down: [4], w_up: [64, 4], b_up: [64]
#define NPLANES   2048        // 32 * 64
#define PLANE_F4  16384       // 65536 / 4
#define TOTAL_F4  33554432    // 2048 * 16384

__device__ float g_pooled[NPLANES];
__device__ float g_scale[NPLANES];

// ---------------------------------------------------------------------------
// Kernel 1: per-plane global average pool. One block per (b,c) plane.
// Default cache policy on loads: the tail of the array stays resident in L2
// for the scale kernel to harvest.
// ---------------------------------------------------------------------------
__global__ void __launch_bounds__(256) se_pool_kernel(const float* __restrict__ x)
{
    const int plane = blockIdx.x;
    const float4* __restrict__ p =
        reinterpret_cast<const float4*>(x) + (size_t)plane * PLANE_F4;

    float sum = 0.0f;
    for (int i = threadIdx.x; i < PLANE_F4; i += 256) {
        float4 v = p[i];
        sum += (v.x + v.y) + (v.z + v.w);
    }

    // warp tree
    #pragma unroll
    for (int o = 16; o > 0; o >>= 1)
        sum += __shfl_xor_sync(0xFFFFFFFFu, sum, o);

    __shared__ float s[8];
    const int lane = threadIdx.x & 31;
    const int w    = threadIdx.x >> 5;
    if (lane == 0) s[w] = sum;
    __syncthreads();
    if (w == 0) {
        sum = (lane < 8) ? s[lane] : 0.0f;
        #pragma unroll
        for (int o = 4; o > 0; o >>= 1)
            sum += __shfl_xor_sync(0xFFFFFFFFu, sum, o);
        if (lane == 0)
            g_pooled[plane] = sum * (1.0f / 65536.0f);
    }
}

// ---------------------------------------------------------------------------
// Kernel 2: SE MLP 64 -> 4 (relu) -> 64 (sigmoid). One block per batch.
// ---------------------------------------------------------------------------
__global__ void __launch_bounds__(64) se_mlp_kernel(
    const float* __restrict__ w_down,  // [4, 64]
    const float* __restrict__ b_down,  // [4]
    const float* __restrict__ w_up,    // [64, 4]
    const float* __restrict__ b_up)    // [64]
{
    const int b = blockIdx.x;   // 0..31
    const int c = threadIdx.x;  // 0..63

    __shared__ float pooled[64];
    __shared__ float hidden[4];

    pooled[c] = g_pooled[b * 64 + c];
    __syncthreads();

    if (c < 4) {
        float h = b_down[c];
        #pragma unroll 8
        for (int k = 0; k < 64; k++)
            h = fmaf(pooled[k], w_down[c * 64 + k], h);
        hidden[c] = fmaxf(h, 0.0f);
    }
    __syncthreads();

    float s = b_up[c];
    #pragma unroll
    for (int m = 0; m < 4; m++)
        s = fmaf(hidden[m], w_up[c * 4 + m], s);

    g_scale[b * 64 + c] = 1.0f / (1.0f + expf(-s));
}

// ---------------------------------------------------------------------------
// Kernel 3: elementwise channel rescale, one float4 per thread.
// REVERSED block order: the pool kernel finished with the high-address tail
// of the array resident in L2, so consume that first (L2 harvest).
// Evict-first loads + streaming stores: no reuse, minimize L2 thrash.
// ---------------------------------------------------------------------------
__global__ void __launch_bounds__(256) se_scale_kernel(
    const float* __restrict__ x, float* __restrict__ y)
{
    const size_t chunk = (size_t)(gridDim.x - 1u - blockIdx.x);
    const size_t i = chunk * 256 + threadIdx.x;                // float4 index
    const float s = g_scale[i >> 14];                          // 16384 f4/plane

    float4 v = __ldcs(reinterpret_cast<const float4*>(x) + i);
    v.x *= s; v.y *= s; v.z *= s; v.w *= s;
    __stcs(reinterpret_cast<float4*>(y) + i, v);
}

// ---------------------------------------------------------------------------
extern "C" void kernel_launch(void* const* d_in, const int* in_sizes, int n_in,
                              void* d_out, int out_size)
{
    const float* trans_b = (const float*)d_in[0];
    const float* w_down  = (const float*)d_in[1];
    const float* b_down  = (const float*)d_in[2];
    const float* w_up    = (const float*)d_in[3];
    const float* b_up    = (const float*)d_in[4];
    float* out = (float*)d_out;

    se_pool_kernel<<<NPLANES, 256>>>(trans_b);
    se_mlp_kernel<<<32, 64>>>(w_down, b_down, w_up, b_up);
    se_scale_kernel<<<TOTAL_F4 / 256, 256>>>(trans_b, out);
}